// round 8
// baseline (speedup 1.0000x reference)
#include <cuda_runtime.h>
#include <cuda_fp16.h>

// Problem constants
#define NW      16384   // words
#define LCH     16      // chars per word
#define CEMB    64      // char emb dim
#define CO      256     // conv out channels
#define DEMB    300     // word emb dim
#define OUTW    556     // 256 + 300
#define OCHUNK  128     // channels per block (blockIdx.y in {0,1})

// Precomputed conv tables (fp16): M[k][c][o] = sum_e char_emb[c,e]*conv_w[o,e,k]
__device__ __half g_Mh[3 * 128 * 256];

// ---------------------------------------------------------------------------
// Kernel 1: build tables. grid = 256 (o), block = 128 (c).
// conv_w reads warp-uniform, vectorized float4; se rows padded to 130 floats.
// ---------------------------------------------------------------------------
__global__ void build_tables_kernel(const float* __restrict__ ce_w,
                                    const float* __restrict__ conv_w) {
    __shared__ float se[64 * 130];   // se[e*130 + c], padded rows
    const int o = blockIdx.x;
    const int c = threadIdx.x;

    for (int i = threadIdx.x; i < 128 * 64; i += 128) {
        int cc = i >> 6;
        int e  = i & 63;
        se[e * 130 + cc] = ce_w[i];
    }
    __syncthreads();

    // conv_w[o][e][k]: 192 floats = 48 float4 (16B-aligned: o*768 bytes)
    const float4* wp4 = reinterpret_cast<const float4*>(conv_w + o * (CEMB * 3));
    float a0 = 0.f, a1 = 0.f, a2 = 0.f;
#pragma unroll
    for (int g = 0; g < 16; ++g) {           // 4 e's per group
        float4 f0 = wp4[3 * g + 0];
        float4 f1 = wp4[3 * g + 1];
        float4 f2 = wp4[3 * g + 2];
        float s0 = se[(4 * g + 0) * 130 + c];
        float s1 = se[(4 * g + 1) * 130 + c];
        float s2 = se[(4 * g + 2) * 130 + c];
        float s3 = se[(4 * g + 3) * 130 + c];
        a0 = fmaf(s0, f0.x, a0); a1 = fmaf(s0, f0.y, a1); a2 = fmaf(s0, f0.z, a2);
        a0 = fmaf(s1, f0.w, a0); a1 = fmaf(s1, f1.x, a1); a2 = fmaf(s1, f1.y, a2);
        a0 = fmaf(s2, f1.z, a0); a1 = fmaf(s2, f1.w, a1); a2 = fmaf(s2, f2.x, a2);
        a0 = fmaf(s3, f2.y, a0); a1 = fmaf(s3, f2.z, a1); a2 = fmaf(s3, f2.w, a2);
    }
    g_Mh[(0 * 128 + c) * 256 + o] = __float2half_rn(a0);
    g_Mh[(1 * 128 + c) * 256 + o] = __float2half_rn(a1);
    g_Mh[(2 * 128 + c) * 256 + o] = __float2half_rn(a2);
}

// ---------------------------------------------------------------------------
// Kernel 2: main. grid = (148, 2), block = 640, 96 KB dyn smem, 2 CTAs/SM.
// Warp = one word; lane = 4 channels (H4). Two INDEPENDENT carry chains per
// word (t=0..7 and t=8..17 with warm-up) for 2x ILP.
// Smem: char row c = 768 B: [k=0: 32 lanes x 8B][k=1][k=2].
// ---------------------------------------------------------------------------
struct H4 { __half2 a, b; };

__device__ __forceinline__ H4 h4add(H4 x, H4 y) {
    H4 r; r.a = __hadd2(x.a, y.a); r.b = __hadd2(x.b, y.b); return r;
}
__device__ __forceinline__ H4 h4max(H4 x, H4 y) {
    H4 r; r.a = __hmax2(x.a, y.a); r.b = __hmax2(x.b, y.b); return r;
}

extern "C" __global__ void __launch_bounds__(640, 2)
wordchar_main_kernel(const int* __restrict__ X,
                     const int* __restrict__ Xword,
                     const float* __restrict__ conv_b,
                     const float* __restrict__ wemb,
                     float* __restrict__ out) {
    extern __shared__ __align__(16) char smem_raw[];

    const int half_id = blockIdx.y;
    const int o_base  = half_id * OCHUNK;

    // stage table into [c][k][lane] rows of 768 B
    {
        const uint2* Mg2 = reinterpret_cast<const uint2*>(g_Mh);
        uint2* Ms2 = reinterpret_cast<uint2*>(smem_raw);
        const int o4 = o_base >> 2;
        const int ntot = 128 * 96;             // 12288 uint2
        for (int i = threadIdx.x; i < ntot; i += blockDim.x) {
            int c  = i / 96;
            int s  = i - c * 96;
            int k  = s >> 5;
            int ln = s & 31;
            Ms2[i] = Mg2[(k * 128 + c) * 64 + o4 + ln];
        }
    }
    __syncthreads();

    const int warp   = threadIdx.x >> 5;
    const int lane   = threadIdx.x & 31;
    const int gwarp  = blockIdx.x * 20 + warp;
    const int nwarps = gridDim.x * 20;

    const float4 b4 = *reinterpret_cast<const float4*>(conv_b + o_base + lane * 4);
    const char* Ms_lane = smem_raw + lane * 8;

    const int j_lo = (half_id == 0) ? 0  : 38;
    const int j_hi = (half_id == 0) ? 38 : 75;

    const H4 zero = { __float2half2_rn(0.f), __float2half2_rn(0.f) };

    for (int w = gwarp; w < NW; w += nwarps) {
        // load 16 chars, pack 4 per register
        const int4* xr = reinterpret_cast<const int4*>(X + w * LCH);
        int4 x0 = xr[0], x1 = xr[1], x2 = xr[2], x3 = xr[3];
        unsigned pk[4];
        pk[0] = (unsigned)x0.x | ((unsigned)x0.y << 8) | ((unsigned)x0.z << 16) | ((unsigned)x0.w << 24);
        pk[1] = (unsigned)x1.x | ((unsigned)x1.y << 8) | ((unsigned)x1.z << 16) | ((unsigned)x1.w << 24);
        pk[2] = (unsigned)x2.x | ((unsigned)x2.y << 8) | ((unsigned)x2.z << 16) | ((unsigned)x2.w << 24);
        pk[3] = (unsigned)x3.x | ((unsigned)x3.y << 8) | ((unsigned)x3.z << 16) | ((unsigned)x3.w << 24);

        // word-embedding gather kicked off early
        const int wi = Xword[w];
        const float4* src = reinterpret_cast<const float4*>(wemb + (size_t)wi * DEMB);
        float4* dst = reinterpret_cast<float4*>(out + (size_t)w * OUTW + CO);
        float4 e0, e1;
        const int j0 = j_lo + lane;
        const int j1 = j_lo + 32 + lane;
        const bool p0 = (j0 < j_hi);
        const bool p1 = (j1 < j_hi);
        if (p0) e0 = src[j0];
        if (p1) e1 = src[j1];

        // ---- chain B warm-up: t=6,7 (m0/m1 only, no max) ----
        H4 c0B, c1B;
        {
            const int c6 = (pk[1] >> 16) & 0xFF;
            const int c7 = (pk[1] >> 24) & 0xFF;
            const char* r6 = Ms_lane + c6 * 768;
            const char* r7 = Ms_lane + c7 * 768;
            H4 m0_6 = *reinterpret_cast<const H4*>(r6);
            H4 m1_6 = *reinterpret_cast<const H4*>(r6 + 256);
            H4 m0_7 = *reinterpret_cast<const H4*>(r7);
            H4 m1_7 = *reinterpret_cast<const H4*>(r7 + 256);
            c1B = h4add(m1_7, m0_6);   // carry into t=8
            c0B = m0_7;
        }

        // ---- interleaved dual chains: A handles t=i, B handles t=i+8 ----
        H4 maxsA, c0A = zero, c1A = zero;
        H4 maxsB;
#pragma unroll
        for (int i = 0; i < 8; ++i) {
            // chain A, t = i
            {
                const int cc = (pk[i >> 2] >> ((i & 3) * 8)) & 0xFF;
                const char* rowp = Ms_lane + cc * 768;
                H4 m0 = *reinterpret_cast<const H4*>(rowp);
                H4 m1 = *reinterpret_cast<const H4*>(rowp + 256);
                H4 m2 = *reinterpret_cast<const H4*>(rowp + 512);
                H4 y  = h4add(m2, c1A);
                maxsA = (i == 0) ? y : h4max(maxsA, y);
                c1A = h4add(m1, c0A);
                c0A = m0;
            }
            // chain B, t = i + 8
            {
                const int t  = i + 8;
                const int cc = (pk[t >> 2] >> ((t & 3) * 8)) & 0xFF;
                const char* rowp = Ms_lane + cc * 768;
                H4 m0 = *reinterpret_cast<const H4*>(rowp);
                H4 m1 = *reinterpret_cast<const H4*>(rowp + 256);
                H4 m2 = *reinterpret_cast<const H4*>(rowp + 512);
                H4 y  = h4add(m2, c1B);
                maxsB = (i == 0) ? y : h4max(maxsB, y);
                c1B = h4add(m1, c0B);
                c0B = m0;
            }
        }
        // chain A tail at t=8,9 is covered by chain B's y[8],y[9] carries.
        // chain B tails: t=16 (c1B), t=17 (c0B)
        maxsB = h4max(maxsB, c1B);
        maxsB = h4max(maxsB, c0B);
        H4 maxs = h4max(maxsA, maxsB);

        // fp32 bias + relu + store
        float2 f0 = __half22float2(maxs.a);
        float2 f1 = __half22float2(maxs.b);
        float4 r;
        r.x = fmaxf(f0.x + b4.x, 0.f);
        r.y = fmaxf(f0.y + b4.y, 0.f);
        r.z = fmaxf(f1.x + b4.z, 0.f);
        r.w = fmaxf(f1.y + b4.w, 0.f);
        *reinterpret_cast<float4*>(out + (size_t)w * OUTW + o_base + lane * 4) = r;

        if (p0) dst[j0] = e0;
        if (p1) dst[j1] = e1;
    }
}

// ---------------------------------------------------------------------------
// Launch
// ---------------------------------------------------------------------------
extern "C" void kernel_launch(void* const* d_in, const int* in_sizes, int n_in,
                              void* d_out, int out_size) {
    const int*   X        = (const int*)  d_in[0];   // [16384,16]
    const int*   X_word   = (const int*)  d_in[1];   // [16384]
    const float* char_emb = (const float*)d_in[2];   // [128,64]
    const float* conv_w   = (const float*)d_in[3];   // [256,64,3]
    const float* conv_b   = (const float*)d_in[4];   // [256]
    const float* word_emb = (const float*)d_in[5];   // [50000,300]
    float*       out      = (float*)d_out;           // [16384,556]

    build_tables_kernel<<<256, 128>>>(char_emb, conv_w);

    const int smem = 128 * 768;                       // 98304 (96 KB)
    cudaFuncSetAttribute(wordchar_main_kernel,
                         cudaFuncAttributeMaxDynamicSharedMemorySize, smem);
    dim3 grid(148, 2);
    wordchar_main_kernel<<<grid, 640, smem>>>(X, X_word, conv_b, word_emb, out);
}

// round 9
// speedup vs baseline: 1.1404x; 1.1404x over previous
#include <cuda_runtime.h>
#include <cuda_fp16.h>

// Problem constants
#define NW      16384   // words
#define LCH     16      // chars per word
#define CEMB    64      // char emb dim
#define CO      256     // conv out channels
#define DEMB    300     // word emb dim
#define OUTW    556     // 256 + 300
#define OCHUNK  128     // channels per block (blockIdx.y in {0,1})
#define WPC     111     // words per CTA (148 * 111 >= 16384)

// Precomputed conv tables (fp16): M[k][c][o] = sum_e char_emb[c,e]*conv_w[o,e,k]
__device__ __half g_Mh[3 * 128 * 256];

// smem layout offsets (bytes)
#define SM_TABLE  0
#define SM_XPK    98304                    // WPC uint4 (packed chars), 1776 B
#define SM_XW     (98304 + WPC * 16)       // WPC ints, 444 B
#define SM_TOTAL  (SM_XW + WPC * 4)

// ---------------------------------------------------------------------------
// Kernel 1: build tables. grid = 256 (o), block = 128 (c).
// ---------------------------------------------------------------------------
__global__ void build_tables_kernel(const float* __restrict__ ce_w,
                                    const float* __restrict__ conv_w) {
    __shared__ float se[64 * 130];   // padded rows: no STS conflicts
    const int o = blockIdx.x;
    const int c = threadIdx.x;

    for (int i = threadIdx.x; i < 128 * 64; i += 128) {
        int cc = i >> 6;
        int e  = i & 63;
        se[e * 130 + cc] = ce_w[i];
    }
    __syncthreads();

    const float4* wp4 = reinterpret_cast<const float4*>(conv_w + o * (CEMB * 3));
    float a0 = 0.f, a1 = 0.f, a2 = 0.f;
#pragma unroll
    for (int g = 0; g < 16; ++g) {
        float4 f0 = wp4[3 * g + 0];
        float4 f1 = wp4[3 * g + 1];
        float4 f2 = wp4[3 * g + 2];
        float s0 = se[(4 * g + 0) * 130 + c];
        float s1 = se[(4 * g + 1) * 130 + c];
        float s2 = se[(4 * g + 2) * 130 + c];
        float s3 = se[(4 * g + 3) * 130 + c];
        a0 = fmaf(s0, f0.x, a0); a1 = fmaf(s0, f0.y, a1); a2 = fmaf(s0, f0.z, a2);
        a0 = fmaf(s1, f0.w, a0); a1 = fmaf(s1, f1.x, a1); a2 = fmaf(s1, f1.y, a2);
        a0 = fmaf(s2, f1.z, a0); a1 = fmaf(s2, f1.w, a1); a2 = fmaf(s2, f2.x, a2);
        a0 = fmaf(s3, f2.y, a0); a1 = fmaf(s3, f2.z, a1); a2 = fmaf(s3, f2.w, a2);
    }
    g_Mh[(0 * 128 + c) * 256 + o] = __float2half_rn(a0);
    g_Mh[(1 * 128 + c) * 256 + o] = __float2half_rn(a1);
    g_Mh[(2 * 128 + c) * 256 + o] = __float2half_rn(a2);
}

// ---------------------------------------------------------------------------
// Kernel 2: main. grid = (148, 2), block = 640, ~98.2 KB dyn smem, 2 CTAs/SM.
// CTA owns a CONTIGUOUS block of WPC words; staging pre-packs its chars into
// smem (4 chars/uint32) so the inner loop has ZERO global loads except the
// prefetched word-embedding gather.
// ---------------------------------------------------------------------------
struct H4 { __half2 a, b; };

__device__ __forceinline__ H4 h4add(H4 x, H4 y) {
    H4 r; r.a = __hadd2(x.a, y.a); r.b = __hadd2(x.b, y.b); return r;
}
__device__ __forceinline__ H4 h4max(H4 x, H4 y) {
    H4 r; r.a = __hmax2(x.a, y.a); r.b = __hmax2(x.b, y.b); return r;
}

extern "C" __global__ void __launch_bounds__(640, 2)
wordchar_main_kernel(const int* __restrict__ X,
                     const int* __restrict__ Xword,
                     const float* __restrict__ conv_b,
                     const float* __restrict__ wemb,
                     float* __restrict__ out) {
    extern __shared__ __align__(16) char smem_raw[];
    uint4* xs_pk4 = reinterpret_cast<uint4*>(smem_raw + SM_XPK);
    unsigned* xs_pk = reinterpret_cast<unsigned*>(smem_raw + SM_XPK);
    int* xw_s = reinterpret_cast<int*>(smem_raw + SM_XW);

    const int half_id = blockIdx.y;
    const int o_base  = half_id * OCHUNK;

    const int base = blockIdx.x * WPC;
    const int cnt  = (NW - base < WPC) ? (NW - base) : WPC;

    // ---- staging: table + this block's packed chars + word ids ----
    {
        const uint2* Mg2 = reinterpret_cast<const uint2*>(g_Mh);
        uint2* Ms2 = reinterpret_cast<uint2*>(smem_raw);
        const int o4 = o_base >> 2;
        const int ntot = 128 * 96;             // 12288 uint2
        for (int i = threadIdx.x; i < ntot; i += blockDim.x) {
            int c  = i / 96;
            int s  = i - c * 96;
            int k  = s >> 5;
            int ln = s & 31;
            Ms2[i] = Mg2[(k * 128 + c) * 64 + o4 + ln];
        }
        // chars: each thread packs one int4 (4 chars) -> one uint32
        const int4* X4 = reinterpret_cast<const int4*>(X);
        for (int i = threadIdx.x; i < cnt * 4; i += blockDim.x) {
            int4 xi = X4[base * 4 + i];        // coalesced
            xs_pk[i] = (unsigned)xi.x | ((unsigned)xi.y << 8) |
                       ((unsigned)xi.z << 16) | ((unsigned)xi.w << 24);
        }
        for (int i = threadIdx.x; i < cnt; i += blockDim.x)
            xw_s[i] = Xword[base + i];
    }
    __syncthreads();

    const int warp = threadIdx.x >> 5;
    const int lane = threadIdx.x & 31;

    const float4 b4 = *reinterpret_cast<const float4*>(conv_b + o_base + lane * 4);
    const char* Ms_lane = smem_raw + lane * 8;

    const int j_lo = (half_id == 0) ? 0  : 38;
    const int j_hi = (half_id == 0) ? 38 : 75;

    const H4 zero = { __float2half2_rn(0.f), __float2half2_rn(0.f) };

    for (int wl = warp; wl < cnt; wl += 20) {
        const int w = base + wl;

        // chars: one broadcast LDS.128
        uint4 pkv = xs_pk4[wl];
        unsigned pk[4] = { pkv.x, pkv.y, pkv.z, pkv.w };

        // word-embedding gather kicked off early (the only LDG in the loop)
        const int wi = xw_s[wl];
        const float4* src = reinterpret_cast<const float4*>(wemb + (size_t)wi * DEMB);
        float4* dst = reinterpret_cast<float4*>(out + (size_t)w * OUTW + CO);
        float4 e0, e1;
        const int j0 = j_lo + lane;
        const int j1 = j_lo + 32 + lane;
        const bool p0 = (j0 < j_hi);
        const bool p1 = (j1 < j_hi);
        if (p0) e0 = src[j0];
        if (p1) e1 = src[j1];

        // ---- chain B warm-up: t=6,7 (m0/m1 only) ----
        H4 c0B, c1B;
        {
            const int c6 = (pk[1] >> 16) & 0xFF;
            const int c7 = (pk[1] >> 24) & 0xFF;
            const char* r6 = Ms_lane + c6 * 768;
            const char* r7 = Ms_lane + c7 * 768;
            H4 m0_6 = *reinterpret_cast<const H4*>(r6);
            H4 m1_6 = *reinterpret_cast<const H4*>(r6 + 256);
            H4 m0_7 = *reinterpret_cast<const H4*>(r7);
            H4 m1_7 = *reinterpret_cast<const H4*>(r7 + 256);
            c1B = h4add(m1_7, m0_6);
            c0B = m0_7;
        }

        // ---- interleaved dual chains: A t=i, B t=i+8 ----
        H4 maxsA, c0A = zero, c1A = zero;
        H4 maxsB;
#pragma unroll
        for (int i = 0; i < 8; ++i) {
            {
                const int cc = (pk[i >> 2] >> ((i & 3) * 8)) & 0xFF;
                const char* rowp = Ms_lane + cc * 768;
                H4 m0 = *reinterpret_cast<const H4*>(rowp);
                H4 m1 = *reinterpret_cast<const H4*>(rowp + 256);
                H4 m2 = *reinterpret_cast<const H4*>(rowp + 512);
                H4 y  = h4add(m2, c1A);
                maxsA = (i == 0) ? y : h4max(maxsA, y);
                c1A = h4add(m1, c0A);
                c0A = m0;
            }
            {
                const int t  = i + 8;
                const int cc = (pk[t >> 2] >> ((t & 3) * 8)) & 0xFF;
                const char* rowp = Ms_lane + cc * 768;
                H4 m0 = *reinterpret_cast<const H4*>(rowp);
                H4 m1 = *reinterpret_cast<const H4*>(rowp + 256);
                H4 m2 = *reinterpret_cast<const H4*>(rowp + 512);
                H4 y  = h4add(m2, c1B);
                maxsB = (i == 0) ? y : h4max(maxsB, y);
                c1B = h4add(m1, c0B);
                c0B = m0;
            }
        }
        maxsB = h4max(maxsB, c1B);   // t = 16
        maxsB = h4max(maxsB, c0B);   // t = 17
        H4 maxs = h4max(maxsA, maxsB);

        // fp32 bias + relu + store
        float2 f0 = __half22float2(maxs.a);
        float2 f1 = __half22float2(maxs.b);
        float4 r;
        r.x = fmaxf(f0.x + b4.x, 0.f);
        r.y = fmaxf(f0.y + b4.y, 0.f);
        r.z = fmaxf(f1.x + b4.z, 0.f);
        r.w = fmaxf(f1.y + b4.w, 0.f);
        *reinterpret_cast<float4*>(out + (size_t)w * OUTW + o_base + lane * 4) = r;

        if (p0) dst[j0] = e0;
        if (p1) dst[j1] = e1;
    }
}

// ---------------------------------------------------------------------------
// Launch
// ---------------------------------------------------------------------------
extern "C" void kernel_launch(void* const* d_in, const int* in_sizes, int n_in,
                              void* d_out, int out_size) {
    const int*   X        = (const int*)  d_in[0];   // [16384,16]
    const int*   X_word   = (const int*)  d_in[1];   // [16384]
    const float* char_emb = (const float*)d_in[2];   // [128,64]
    const float* conv_w   = (const float*)d_in[3];   // [256,64,3]
    const float* conv_b   = (const float*)d_in[4];   // [256]
    const float* word_emb = (const float*)d_in[5];   // [50000,300]
    float*       out      = (float*)d_out;           // [16384,556]

    build_tables_kernel<<<256, 128>>>(char_emb, conv_w);

    cudaFuncSetAttribute(wordchar_main_kernel,
                         cudaFuncAttributeMaxDynamicSharedMemorySize, SM_TOTAL);
    dim3 grid(148, 2);
    wordchar_main_kernel<<<grid, 640, SM_TOTAL>>>(X, X_word, conv_b, word_emb, out);
}